// round 1
// baseline (speedup 1.0000x reference)
#include <cuda_runtime.h>

// Problem constants (fixed by the dataset)
#define KN 131072   // rows of x
#define KK 16       // experts
#define KM 128      // affine pieces per expert
#define KD 64       // feature dim
#define BN 64       // n-rows per block

typedef unsigned long long u64;

// ---- packed f32x2 helpers (Blackwell sm_103a packed fp32 pipe) ----
__device__ __forceinline__ u64 pack2(float lo, float hi) {
    u64 r; asm("mov.b64 %0, {%1, %2};" : "=l"(r) : "f"(lo), "f"(hi)); return r;
}
__device__ __forceinline__ void unpack2(u64 v, float& lo, float& hi) {
    asm("mov.b64 {%0, %1}, %2;" : "=f"(lo), "=f"(hi) : "l"(v));
}
__device__ __forceinline__ u64 ffma2(u64 a, u64 b, u64 c) {
    u64 d;
    asm("fma.rn.f32x2 %0, %1, %2, %3;" : "=l"(d) : "l"(a), "l"(b), "l"(c));
    return d;
}

// Each block: 64 n-rows, all 128 m-columns, loop over 16 experts.
// Thread grid 16(m) x 16(n). Per thread: 4 n-rows x 8 m-cols.
// m fragment mapping m = g*32 + 2*mIdx + j (g<4, j<2) keeps the 4
// LDS.128 a-fragment loads bank-conflict-free (16 lanes read 256B
// consecutive per instruction).
__global__ __launch_bounds__(256, 2)
void madk(const float* __restrict__ x, const float* __restrict__ s,
          const float* __restrict__ a, const float* __restrict__ b,
          float* __restrict__ out)
{
    // packed (even d, odd d) planes: element [d2][i] = (v[2*d2], v[2*d2+1])
    __shared__ u64 xs[KD / 2][BN];   // 16 KB
    __shared__ u64 as_[KD / 2][KM];  // 32 KB  (total 48 KB static)

    const int tid   = threadIdx.x;
    const int mIdx  = tid & 15;
    const int nIdx  = tid >> 4;
    const int rowBase = blockIdx.x * BN;
    const int n0    = nIdx * 4;
    const int mBase = mIdx * 2;

    // ---- load x tile once per block (reused for all 16 experts) ----
    {
        const float4* xg = reinterpret_cast<const float4*>(x + (size_t)rowBase * KD);
        #pragma unroll
        for (int i = 0; i < 4; ++i) {
            int idx = tid + i * 256;          // 1024 float4 total
            float4 v = xg[idx];
            int r = idx >> 4, c4 = idx & 15;  // row, float4-column (d = 4*c4)
            xs[2 * c4][r]     = pack2(v.x, v.y);
            xs[2 * c4 + 1][r] = pack2(v.z, v.w);
        }
    }

    float res[4] = {0.f, 0.f, 0.f, 0.f};

    for (int k = 0; k < KK; ++k) {
        __syncthreads();  // previous iteration done with as_, xs visible
        {
            const float4* ag = reinterpret_cast<const float4*>(a + (size_t)k * KM * KD);
            #pragma unroll
            for (int i = 0; i < 8; ++i) {
                int idx = tid + i * 256;      // 2048 float4 total
                float4 v = ag[idx];
                int r = idx >> 4, c4 = idx & 15;
                as_[2 * c4][r]     = pack2(v.x, v.y);
                as_[2 * c4 + 1][r] = pack2(v.z, v.w);
            }
        }
        __syncthreads();

        u64 acc[4][8];
        #pragma unroll
        for (int i = 0; i < 4; ++i)
            #pragma unroll
            for (int j = 0; j < 8; ++j)
                acc[i][j] = 0ull;

        // ---- main GEMM loop over packed d pairs ----
        #pragma unroll 8
        for (int d2 = 0; d2 < KD / 2; ++d2) {
            u64 xv[4], av[8];
            #pragma unroll
            for (int i = 0; i < 4; ++i) xv[i] = xs[d2][n0 + i];
            #pragma unroll
            for (int g = 0; g < 4; ++g) {
                av[2 * g]     = as_[d2][g * 32 + mBase];
                av[2 * g + 1] = as_[d2][g * 32 + mBase + 1];
            }
            #pragma unroll
            for (int i = 0; i < 4; ++i)
                #pragma unroll
                for (int j = 0; j < 8; ++j)
                    acc[i][j] = ffma2(xv[i], av[j], acc[i][j]);
        }

        // ---- fused epilogue: logsumexp over m (128 cols spread over 16 lanes) ----
        const float sv = __ldg(s + k);
        float bb[8];
        #pragma unroll
        for (int g = 0; g < 4; ++g) {
            bb[2 * g]     = __ldg(b + k * KM + g * 32 + mBase);
            bb[2 * g + 1] = __ldg(b + k * KM + g * 32 + mBase + 1);
        }

        #pragma unroll
        for (int i = 0; i < 4; ++i) {
            float sc[8];
            #pragma unroll
            for (int j = 0; j < 8; ++j) {
                float lo, hi; unpack2(acc[i][j], lo, hi);
                sc[j] = lo + hi + bb[j];
            }
            float mx = sc[0];
            #pragma unroll
            for (int j = 1; j < 8; ++j) mx = fmaxf(mx, sc[j]);
            // reduce over 16 lanes sharing this n-row (xor<=8 stays in half-warp)
            #pragma unroll
            for (int o = 1; o < 16; o <<= 1)
                mx = fmaxf(mx, __shfl_xor_sync(0xffffffffu, mx, o, 32));
            float sum = 0.f;
            #pragma unroll
            for (int j = 0; j < 8; ++j) sum += __expf(sc[j] - mx);
            #pragma unroll
            for (int o = 1; o < 16; o <<= 1)
                sum += __shfl_xor_sync(0xffffffffu, sum, o, 32);
            res[i] = fmaf(sv, mx + __logf(sum), res[i]);
        }
    }

    if (mIdx == 0) {
        #pragma unroll
        for (int i = 0; i < 4; ++i)
            out[rowBase + n0 + i] = res[i];
    }
}

extern "C" void kernel_launch(void* const* d_in, const int* in_sizes, int n_in,
                              void* d_out, int out_size)
{
    const float* x = (const float*)d_in[0];   // [131072, 64]
    const float* s = (const float*)d_in[1];   // [16]
    const float* a = (const float*)d_in[2];   // [16, 128, 64]
    const float* b = (const float*)d_in[3];   // [16, 128]
    float* out = (float*)d_out;               // [131072]

    madk<<<KN / BN, 256>>>(x, s, a, b, out);
}

// round 3
// speedup vs baseline: 4.8197x; 4.8197x over previous
#include <cuda_runtime.h>
#include <cuda_bf16.h>
#include <cstdint>

#define KN 131072
#define KK 16
#define KM 128
#define KD 64
#define BN 128      // n-rows per CTA
#define XPAD 68     // x_sm row stride (floats); 272B = 17*16B keeps float4 alignment, kills conflicts

// Pre-split, pre-fragment-arranged 'a': [k][split(hi/lo)][kstep(4)][mtile(16)][lane(32)][reg(2)] u32
__device__ __align__(16) uint32_t g_b[KK * 8192];   // 512 KB, L2-resident

__device__ __forceinline__ uint32_t pack_bf(__nv_bfloat16 a, __nv_bfloat16 b) {
    return (uint32_t)__bfloat16_as_ushort(a) | ((uint32_t)__bfloat16_as_ushort(b) << 16);
}

// one thread per output u32 (131072 total)
__global__ void prep(const float* __restrict__ a) {
    int idx = blockIdx.x * 256 + threadIdx.x;
    int r  = idx & 1;
    int l  = (idx >> 1) & 31;
    int mt = (idx >> 6) & 15;
    int ks = (idx >> 10) & 3;
    int sp = (idx >> 12) & 1;
    int k  = idx >> 13;
    int m  = mt * 8 + (l >> 2);
    int d0 = ks * 16 + (l & 3) * 2 + r * 8;
    const float* am = a + ((size_t)k * KM + m) * KD + d0;
    float v0 = am[0], v1 = am[1];
    __nv_bfloat16 h0 = __float2bfloat16(v0), h1 = __float2bfloat16(v1);
    uint32_t o;
    if (sp == 0) {
        o = pack_bf(h0, h1);
    } else {
        __nv_bfloat16 l0 = __float2bfloat16(v0 - __bfloat162float(h0));
        __nv_bfloat16 l1 = __float2bfloat16(v1 - __bfloat162float(h1));
        o = pack_bf(l0, l1);
    }
    g_b[idx] = o;
}

// ---- PTX helpers (all base-arch sm_103-legal) ----
__device__ __forceinline__ void mma16816(float (&c)[4], const uint32_t (&A)[4],
                                         uint32_t b0, uint32_t b1) {
    asm volatile(
        "mma.sync.aligned.m16n8k16.row.col.f32.bf16.bf16.f32 "
        "{%0,%1,%2,%3}, {%4,%5,%6,%7}, {%8,%9}, {%0,%1,%2,%3};"
        : "+f"(c[0]), "+f"(c[1]), "+f"(c[2]), "+f"(c[3])
        : "r"(A[0]), "r"(A[1]), "r"(A[2]), "r"(A[3]), "r"(b0), "r"(b1));
}
__device__ __forceinline__ uint32_t smem_u32(const void* p) {
    uint32_t a;
    asm("{ .reg .u64 t; cvta.to.shared.u64 t, %1; cvt.u32.u64 %0, t; }" : "=r"(a) : "l"(p));
    return a;
}
__device__ __forceinline__ void cp16(uint32_t s, const void* g) {
    asm volatile("cp.async.cg.shared.global [%0], [%1], 16;" :: "r"(s), "l"(g));
}

// SMEM layout (bytes): x_sm [BN*XPAD f32] | abuf0 32KB | abuf1 32KB | bsm 8KB
#define XSM_BYTES (BN * XPAD * 4)        // 34816 (16B multiple)
#define ABUF_OFF  XSM_BYTES
#define BSM_OFF   (ABUF_OFF + 65536)
#define DYN_SMEM  (BSM_OFF + KK * KM * 4)

__global__ __launch_bounds__(256, 2)
void madk2(const float* __restrict__ x, const float* __restrict__ s,
           const float* __restrict__ b, float* __restrict__ out)
{
    extern __shared__ __align__(16) char smem[];
    float* x_sm = (float*)smem;
    char*  ab0  = smem + ABUF_OFF;
    float* bsm  = (float*)(smem + BSM_OFF);

    const int tid = threadIdx.x;
    const int w = tid >> 5, l = tid & 31;
    const int g = l >> 2, q = l & 3;
    const uint32_t ab_u32[2] = { smem_u32(ab0), smem_u32(ab0 + 32768) };

    // ---- prefetch expert 0 a-tile (overlaps x staging) ----
    {
        const char* src = (const char*)g_b;
        #pragma unroll
        for (int i = 0; i < 8; ++i) {
            int o = (tid + i * 256) * 16;
            cp16(ab_u32[0] + o, src + o);
        }
        asm volatile("cp.async.commit_group;" ::: "memory");
    }

    // ---- b table ----
    #pragma unroll
    for (int i = 0; i < 8; ++i) bsm[tid + i * 256] = b[tid + i * 256];

    // ---- stage x tile (coalesced, padded rows) ----
    {
        const float4* xg = (const float4*)(x + (size_t)blockIdx.x * BN * KD);
        #pragma unroll
        for (int i = 0; i < 8; ++i) {
            int f = tid + i * 256;              // 2048 float4
            float4 v = xg[f];
            int row = f >> 4, c4 = f & 15;
            *(float4*)(x_sm + row * XPAD + c4 * 4) = v;
        }
    }
    __syncthreads();

    // ---- extract A fragments (hi/lo bf16) for this warp's 16 rows; reused for all experts ----
    uint32_t Ahi[4][4], Alo[4][4];
    {
        const int row0 = w * 16 + g;
        #pragma unroll
        for (int ks = 0; ks < 4; ++ks) {
            #pragma unroll
            for (int h = 0; h < 2; ++h) {        // d-halves -> regs (a0,a1) / (a2,a3)
                int d = ks * 16 + q * 2 + h * 8;
                float2 v0 = *(const float2*)(x_sm + row0 * XPAD + d);
                float2 v1 = *(const float2*)(x_sm + (row0 + 8) * XPAD + d);
                __nv_bfloat16 h00 = __float2bfloat16(v0.x), h01 = __float2bfloat16(v0.y);
                __nv_bfloat16 h10 = __float2bfloat16(v1.x), h11 = __float2bfloat16(v1.y);
                Ahi[ks][h * 2 + 0] = pack_bf(h00, h01);
                Ahi[ks][h * 2 + 1] = pack_bf(h10, h11);
                Alo[ks][h * 2 + 0] = pack_bf(__float2bfloat16(v0.x - __bfloat162float(h00)),
                                             __float2bfloat16(v0.y - __bfloat162float(h01)));
                Alo[ks][h * 2 + 1] = pack_bf(__float2bfloat16(v1.x - __bfloat162float(h10)),
                                             __float2bfloat16(v1.y - __bfloat162float(h11)));
            }
        }
    }

    float res0 = 0.f, res1 = 0.f;

    #pragma unroll 1
    for (int k = 0; k < KK; ++k) {
        asm volatile("cp.async.wait_group 0;" ::: "memory");
        __syncthreads();   // a[k] visible to all; everyone done with buffer (k+1)&1

        if (k + 1 < KK) {  // prefetch next expert, overlapping this expert's MMA
            const char* src = (const char*)(g_b + (size_t)(k + 1) * 8192);
            uint32_t dst = ab_u32[(k + 1) & 1];
            #pragma unroll
            for (int i = 0; i < 8; ++i) {
                int o = (tid + i * 256) * 16;
                cp16(dst + o, src + o);
            }
            asm volatile("cp.async.commit_group;" ::: "memory");
        }

        const char* ab = (k & 1) ? (ab0 + 32768) : ab0;
        const float* bk = bsm + k * KM;
        float s0 = 0.f, s1 = 0.f;

        #pragma unroll
        for (int ch = 0; ch < 4; ++ch) {
            float acc[4][4];
            #pragma unroll
            for (int mt = 0; mt < 4; ++mt)
                #pragma unroll
                for (int j = 0; j < 4; ++j) acc[mt][j] = 0.f;

            #pragma unroll
            for (int ks = 0; ks < 4; ++ks) {
                #pragma unroll
                for (int mt = 0; mt < 4; ++mt) {
                    int mtg = ch * 4 + mt;
                    uint2 bh = *(const uint2*)(ab + (size_t)(((0 * 4 + ks) * 16 + mtg) * 32 + l) * 8);
                    uint2 bl = *(const uint2*)(ab + (size_t)(((1 * 4 + ks) * 16 + mtg) * 32 + l) * 8);
                    mma16816(acc[mt], Ahi[ks], bh.x, bh.y);   // hi*hi
                    mma16816(acc[mt], Ahi[ks], bl.x, bl.y);   // hi*lo
                    mma16816(acc[mt], Alo[ks], bh.x, bh.y);   // lo*hi
                }
            }
            // fused epilogue for this 32-column chunk (no max-sub: scores bounded)
            #pragma unroll
            for (int mt = 0; mt < 4; ++mt) {
                int m0 = (ch * 4 + mt) * 8 + q * 2;
                float2 bb = *(const float2*)(bk + m0);
                s0 += __expf(acc[mt][0] + bb.x);
                s0 += __expf(acc[mt][1] + bb.y);
                s1 += __expf(acc[mt][2] + bb.x);
                s1 += __expf(acc[mt][3] + bb.y);
            }
        }

        // reduce exp-sums across the 4 lanes sharing each n-row (q bits)
        s0 += __shfl_xor_sync(0xffffffffu, s0, 1);
        s0 += __shfl_xor_sync(0xffffffffu, s0, 2);
        s1 += __shfl_xor_sync(0xffffffffu, s1, 1);
        s1 += __shfl_xor_sync(0xffffffffu, s1, 2);

        float sv = __ldg(s + k);
        res0 = fmaf(sv, __logf(s0), res0);
        res1 = fmaf(sv, __logf(s1), res1);
    }

    if (q == 0) {
        int base = blockIdx.x * BN + w * 16 + g;
        out[base]     = res0;
        out[base + 8] = res1;
    }
}

extern "C" void kernel_launch(void* const* d_in, const int* in_sizes, int n_in,
                              void* d_out, int out_size)
{
    const float* x = (const float*)d_in[0];   // [131072, 64]
    const float* s = (const float*)d_in[1];   // [16]
    const float* a = (const float*)d_in[2];   // [16, 128, 64]
    const float* b = (const float*)d_in[3];   // [16, 128]
    float* out = (float*)d_out;

    cudaFuncSetAttribute(madk2, cudaFuncAttributeMaxDynamicSharedMemorySize, DYN_SMEM);

    prep<<<KK * 8192 / 256, 256>>>(a);
    madk2<<<KN / BN, 256, DYN_SMEM>>>(x, s, b, out);
}